// round 1
// baseline (speedup 1.0000x reference)
#include <cuda_runtime.h>
#include <math.h>

#define B_   4
#define S_   2048
#define H_   16
#define DH   64
#define DM   1024
#define MTOT (B_*S_)   // 8192

// Scratch (static device globals — allocation-free)
__device__ float g_q[(size_t)B_*H_*S_*DH];   // [B][H][S][DH]
__device__ float g_k[(size_t)B_*H_*S_*DH];
__device__ float g_v[(size_t)B_*H_*S_*DH];
__device__ float g_o[(size_t)B_*S_*DM];      // attention out, [B][S][H*DH]

// ---------------------------------------------------------------------------
// Tiled SGEMM: C[M=8192, N=1024] = A[M,K=1024] @ W + bias
// WMODE 0: W is [H][K][64] blocked (QKV proj), output scattered to [B][H][S][DH]
// WMODE 1: W is [K][N] dense (O proj), output dense [M][N]
// BM=BN=64, BK=16, 128 threads, 4x8 microtile per thread.
// ---------------------------------------------------------------------------
template<int WMODE>
__global__ void gemm64(const float* __restrict__ A, const float* __restrict__ W,
                       const float* __restrict__ bias, float* __restrict__ out)
{
    __shared__ float As[16][68];   // transposed: As[k][m], pad 68 keeps float4 align
    __shared__ float Ws[16][64];   // Ws[k][n]

    const int tid = threadIdx.x;         // 128 threads
    const int ty  = tid >> 3;            // 0..15 -> 4 rows each
    const int tx  = tid & 7;             // 0..7  -> 8 cols each
    const int m0  = blockIdx.y * 64;
    const int n0  = blockIdx.x * 64;

    float acc[4][8];
#pragma unroll
    for (int i = 0; i < 4; i++)
#pragma unroll
        for (int j = 0; j < 8; j++) acc[i][j] = 0.f;

    for (int k0 = 0; k0 < DM; k0 += 16) {
        // Load A tile 64x16 (transposed into smem)
#pragma unroll
        for (int it = 0; it < 2; it++) {
            int idx = tid + it * 128;           // 0..255 float4s
            int r   = idx >> 2;                 // 0..63 row
            int c4  = (idx & 3) * 4;            // col within 16
            float4 xv = *(const float4*)(A + (size_t)(m0 + r) * DM + k0 + c4);
            As[c4 + 0][r] = xv.x; As[c4 + 1][r] = xv.y;
            As[c4 + 2][r] = xv.z; As[c4 + 3][r] = xv.w;
        }
        // Load W tile 16x64
#pragma unroll
        for (int it = 0; it < 2; it++) {
            int idx = tid + it * 128;           // 0..255 float4s
            int r   = idx >> 4;                 // 0..15 k-row
            int c4  = (idx & 15) * 4;           // 0..60
            const float* wp;
            if (WMODE == 0) {
                int h = n0 >> 6;                // whole 64-wide tile within one head
                wp = W + (size_t)h * DM * 64 + (size_t)(k0 + r) * 64 + c4;
            } else {
                wp = W + (size_t)(k0 + r) * DM + n0 + c4;
            }
            *(float4*)&Ws[r][c4] = *(const float4*)wp;
        }
        __syncthreads();

#pragma unroll
        for (int kk = 0; kk < 16; kk++) {
            float4 a4 = *(const float4*)&As[kk][ty * 4];
            float b[8];
            *(float4*)&b[0] = *(const float4*)&Ws[kk][tx * 8];
            *(float4*)&b[4] = *(const float4*)&Ws[kk][tx * 8 + 4];
            float a[4] = {a4.x, a4.y, a4.z, a4.w};
#pragma unroll
            for (int i = 0; i < 4; i++)
#pragma unroll
                for (int j = 0; j < 8; j++)
                    acc[i][j] = fmaf(a[i], b[j], acc[i][j]);
        }
        __syncthreads();
    }

    // Epilogue
#pragma unroll
    for (int i = 0; i < 4; i++) {
        int m = m0 + ty * 4 + i;
#pragma unroll
        for (int j = 0; j < 8; j++) {
            int n = n0 + tx * 8 + j;
            float val = acc[i][j] + bias[n];
            if (WMODE == 0) {
                int b = m >> 11, s = m & (S_ - 1);
                int h = n >> 6,  e = n & 63;
                out[(((size_t)b * H_ + h) * S_ + s) * DH + e] = val;
            } else {
                out[(size_t)m * DM + n] = val;
            }
        }
    }
}

// ---------------------------------------------------------------------------
// Flash attention, fp32. One block = one (b,h) x 64-query tile.
// 128 threads: ty=tid/8 -> 4 queries, tx=tid%8 -> 8 key-cols / 8 out-dims.
// Smem: Qs[d][q] 64x68, Ks[d][k] 64x68, Pt[k][q] 64x65, Vs[k][d] 64x64
// ---------------------------------------------------------------------------
__global__ void attn64(const float* __restrict__ Q, const float* __restrict__ K,
                       const float* __restrict__ V, float* __restrict__ O)
{
    extern __shared__ float sm[];
    float* Qs = sm;                  // 64*68
    float* Ks = Qs + 64 * 68;        // 64*68
    float* Pt = Ks + 64 * 68;        // 64*65
    float* Vs = Pt + 64 * 65;        // 64*64

    const int tid = threadIdx.x;
    const int ty  = tid >> 3;        // 0..15
    const int tx  = tid & 7;         // 0..7
    const int bh  = blockIdx.y;      // 0..63
    const int q0  = blockIdx.x * 64;

    const float* Qp = Q + ((size_t)bh * S_ + q0) * DH;
    const float* Kp = K + (size_t)bh * S_ * DH;
    const float* Vp = V + (size_t)bh * S_ * DH;

    // Load Q tile transposed: Qs[d][q]
#pragma unroll
    for (int it = 0; it < 8; it++) {
        int idx = tid + it * 128;          // 0..1023 float4s
        int r   = idx >> 4;                // 0..63 query
        int c4  = (idx & 15) * 4;          // 0..60 dim
        float4 v = *(const float4*)(Qp + (size_t)r * DH + c4);
        Qs[(c4 + 0) * 68 + r] = v.x; Qs[(c4 + 1) * 68 + r] = v.y;
        Qs[(c4 + 2) * 68 + r] = v.z; Qs[(c4 + 3) * 68 + r] = v.w;
    }

    float m[4], l[4], acc[4][8];
#pragma unroll
    for (int i = 0; i < 4; i++) {
        m[i] = -INFINITY; l[i] = 0.f;
#pragma unroll
        for (int j = 0; j < 8; j++) acc[i][j] = 0.f;
    }

    for (int kt = 0; kt < S_; kt += 64) {
        __syncthreads();   // previous PV reads done (also covers Q-load, iter 0)
        // Load K tile transposed Ks[d][k], V tile straight Vs[k][d]
#pragma unroll
        for (int it = 0; it < 8; it++) {
            int idx = tid + it * 128;
            int r   = idx >> 4;            // key row 0..63
            int c4  = (idx & 15) * 4;      // dim 0..60
            float4 kv = *(const float4*)(Kp + (size_t)(kt + r) * DH + c4);
            Ks[(c4 + 0) * 68 + r] = kv.x; Ks[(c4 + 1) * 68 + r] = kv.y;
            Ks[(c4 + 2) * 68 + r] = kv.z; Ks[(c4 + 3) * 68 + r] = kv.w;
            float4 vv = *(const float4*)(Vp + (size_t)(kt + r) * DH + c4);
            *(float4*)&Vs[r * 64 + c4] = vv;
        }
        __syncthreads();

        // Scores: s[i][j] = sum_d Q[q][d]*K[k][d]
        float s[4][8];
#pragma unroll
        for (int i = 0; i < 4; i++)
#pragma unroll
            for (int j = 0; j < 8; j++) s[i][j] = 0.f;

#pragma unroll 16
        for (int kk = 0; kk < 64; kk++) {
            float4 a4 = *(const float4*)&Qs[kk * 68 + ty * 4];
            float b[8];
            *(float4*)&b[0] = *(const float4*)&Ks[kk * 68 + tx * 8];
            *(float4*)&b[4] = *(const float4*)&Ks[kk * 68 + tx * 8 + 4];
            float a[4] = {a4.x, a4.y, a4.z, a4.w};
#pragma unroll
            for (int i = 0; i < 4; i++)
#pragma unroll
                for (int j = 0; j < 8; j++)
                    s[i][j] = fmaf(a[i], b[j], s[i][j]);
        }

        // Online softmax update (per query row; 8 tx threads share a row)
#pragma unroll
        for (int i = 0; i < 4; i++) {
            float tmax = -INFINITY;
#pragma unroll
            for (int j = 0; j < 8; j++) {
                s[i][j] *= 0.125f;   // 1/sqrt(64)
                tmax = fmaxf(tmax, s[i][j]);
            }
            tmax = fmaxf(tmax, __shfl_xor_sync(0xffffffffu, tmax, 1));
            tmax = fmaxf(tmax, __shfl_xor_sync(0xffffffffu, tmax, 2));
            tmax = fmaxf(tmax, __shfl_xor_sync(0xffffffffu, tmax, 4));
            float mnew = fmaxf(m[i], tmax);
            float psum = 0.f;
#pragma unroll
            for (int j = 0; j < 8; j++) {
                float p = __expf(s[i][j] - mnew);
                s[i][j] = p;
                psum += p;
            }
            psum += __shfl_xor_sync(0xffffffffu, psum, 1);
            psum += __shfl_xor_sync(0xffffffffu, psum, 2);
            psum += __shfl_xor_sync(0xffffffffu, psum, 4);
            float fac = __expf(m[i] - mnew);
            l[i] = l[i] * fac + psum;
            m[i] = mnew;
#pragma unroll
            for (int j = 0; j < 8; j++) acc[i][j] *= fac;
            // stash P transposed: Pt[k][q]
#pragma unroll
            for (int j = 0; j < 8; j++)
                Pt[(tx * 8 + j) * 65 + ty * 4 + i] = s[i][j];
        }
        __syncthreads();

        // acc[i][j] += sum_k P[q][k] * V[k][d]
#pragma unroll 16
        for (int k = 0; k < 64; k++) {
            float p[4];
#pragma unroll
            for (int i = 0; i < 4; i++) p[i] = Pt[k * 65 + ty * 4 + i];
            float b[8];
            *(float4*)&b[0] = *(const float4*)&Vs[k * 64 + tx * 8];
            *(float4*)&b[4] = *(const float4*)&Vs[k * 64 + tx * 8 + 4];
#pragma unroll
            for (int i = 0; i < 4; i++)
#pragma unroll
                for (int j = 0; j < 8; j++)
                    acc[i][j] = fmaf(p[i], b[j], acc[i][j]);
        }
    }

    // Write output: O[b][q][h*64 + d]
    const int b = bh >> 4, h = bh & 15;
#pragma unroll
    for (int i = 0; i < 4; i++) {
        float inv = 1.f / l[i];
        int q = q0 + ty * 4 + i;
        float* op = O + ((size_t)b * S_ + q) * DM + h * DH + tx * 8;
#pragma unroll
        for (int j = 0; j < 8; j++) op[j] = acc[i][j] * inv;
    }
}

// ---------------------------------------------------------------------------
extern "C" void kernel_launch(void* const* d_in, const int* in_sizes, int n_in,
                              void* d_out, int out_size)
{
    (void)in_sizes; (void)n_in; (void)out_size;
    const float* x  = (const float*)d_in[0];
    const float* WQ = (const float*)d_in[1];
    const float* WK = (const float*)d_in[2];
    const float* WV = (const float*)d_in[3];
    const float* WO = (const float*)d_in[4];
    const float* bQ = (const float*)d_in[5];
    const float* bK = (const float*)d_in[6];
    const float* bV = (const float*)d_in[7];
    const float* bO = (const float*)d_in[8];
    float* out = (float*)d_out;

    void *pq, *pk, *pv, *po;
    cudaGetSymbolAddress(&pq, g_q);
    cudaGetSymbolAddress(&pk, g_k);
    cudaGetSymbolAddress(&pv, g_v);
    cudaGetSymbolAddress(&po, g_o);

    static int smem_set = 0;
    const int attn_smem = (64 * 68 * 2 + 64 * 65 + 64 * 64) * 4;  // 67840 B
    if (!smem_set) {
        cudaFuncSetAttribute(attn64, cudaFuncAttributeMaxDynamicSharedMemorySize,
                             attn_smem);
        smem_set = 1;
    }

    dim3 ggrid(DM / 64, MTOT / 64);   // (16, 128)
    gemm64<0><<<ggrid, 128>>>(x, WQ, bQ, (float*)pq);
    gemm64<0><<<ggrid, 128>>>(x, WK, bK, (float*)pk);
    gemm64<0><<<ggrid, 128>>>(x, WV, bV, (float*)pv);

    dim3 agrid(S_ / 64, B_ * H_);     // (32, 64)
    attn64<<<agrid, 128, attn_smem>>>((const float*)pq, (const float*)pk,
                                      (const float*)pv, (float*)po);

    gemm64<1><<<ggrid, 128>>>((const float*)po, WO, bO, out);
}

// round 3
// speedup vs baseline: 1.7236x; 1.7236x over previous
#include <cuda_runtime.h>
#include <math.h>
#include <stdint.h>

#define B_   4
#define S_   2048
#define H_   16
#define DH   64
#define DM   1024
#define MTOT (B_*S_)   // 8192

// -------------------------- device scratch (no allocs) ---------------------
__device__ float g_q[(size_t)B_*H_*S_*DH];   // [B][H][S][DH]
__device__ float g_k[(size_t)B_*H_*S_*DH];
__device__ float g_v[(size_t)B_*H_*S_*DH];
__device__ float g_o[(size_t)B_*S_*DM];      // attention out [B][S][H*DH]

__device__ __forceinline__ uint32_t f2tf(float x) {   // round-to-nearest tf32
    uint32_t r;
    asm("cvt.rna.tf32.f32 %0, %1;" : "=r"(r) : "f"(x));
    return r;
}
__device__ __forceinline__ void mma_tf32(float c[4], const uint32_t a[4],
                                         const uint32_t b[2]) {
    asm volatile(
        "mma.sync.aligned.m16n8k8.row.col.f32.tf32.tf32.f32 "
        "{%0,%1,%2,%3}, {%4,%5,%6,%7}, {%8,%9}, {%0,%1,%2,%3};"
        : "+f"(c[0]), "+f"(c[1]), "+f"(c[2]), "+f"(c[3])
        : "r"(a[0]), "r"(a[1]), "r"(a[2]), "r"(a[3]), "r"(b[0]), "r"(b[1]));
}

// ---------------------------------------------------------------------------
// Tensor-core tf32 GEMM: C[M=8192, N=1024] = A[M,K=1024] @ B[K,N] + bias[n]
// WMODE 0: B = W_QKV [H][K][64]  (B[k][n] with n = h*64+e), scatter out to
//          [B][H][S][DH].
// WMODE 1: B = W_O dense [K=H*DH][N=DM], dense out [M][DM].
// Block 128x128, BK=32, 256 threads (8 warps, 4x2), warp tile 32x64.
// Double-buffered smem; padded layouts -> conflict-free fragment LDS.
// ---------------------------------------------------------------------------
#define PAD_A 36          // As row stride (floats): banks 4*gr+gc distinct
#define PAD_W 136         // Ws row stride (floats): banks 8*gc+n distinct
#define ASZ (128 * PAD_A) // floats per A buffer
#define WSZ (32 * PAD_W)  // floats per W buffer
#define GSMEM ((2 * (ASZ + WSZ)) * 4)   // 71680 bytes
#define NKT (DM / 32)     // 32 k-tiles

template<int WMODE>
__device__ __forceinline__ void stage_tiles(
    const float* __restrict__ A, const float* __restrict__ W,
    float* __restrict__ as, float* __restrict__ ws,
    int m0, int n0, int k0, int tid)
{
    // A tile: 128 rows x 32 k (tf32-converted)
#pragma unroll
    for (int i = 0; i < 4; i++) {
        int idx = tid + i * 256;          // 0..1023 float4s
        int r   = idx >> 3;               // 0..127
        int c4  = (idx & 7) << 2;         // 0,4,..,28
        float4 v = *(const float4*)(A + (size_t)(m0 + r) * DM + k0 + c4);
        float4 o;
        o.x = __uint_as_float(f2tf(v.x)); o.y = __uint_as_float(f2tf(v.y));
        o.z = __uint_as_float(f2tf(v.z)); o.w = __uint_as_float(f2tf(v.w));
        *(float4*)(as + r * PAD_A + c4) = o;   // 144B row stride: 16B aligned
    }
    // W tile: 32 k-rows x 128 n (tf32-converted)
#pragma unroll
    for (int i = 0; i < 4; i++) {
        int idx = tid + i * 256;
        int r   = idx >> 5;               // 0..31 (k)
        int c4  = (idx & 31) << 2;        // 0..124 (n)
        const float* wp;
        if (WMODE == 0) {
            int n = n0 + c4, h = n >> 6, e = n & 63;
            wp = W + ((size_t)h * DM + (k0 + r)) * 64 + e;
        } else {
            wp = W + (size_t)(k0 + r) * DM + n0 + c4;
        }
        float4 v = *(const float4*)wp;
        float4 o;
        o.x = __uint_as_float(f2tf(v.x)); o.y = __uint_as_float(f2tf(v.y));
        o.z = __uint_as_float(f2tf(v.z)); o.w = __uint_as_float(f2tf(v.w));
        *(float4*)(ws + r * PAD_W + c4) = o;   // 544B row stride: 16B aligned
    }
}

template<int WMODE>
__global__ void __launch_bounds__(256, 2)
gemm_mma(const float* __restrict__ A, const float* __restrict__ W,
         const float* __restrict__ bias, float* __restrict__ out)
{
    extern __shared__ float sm[];
    float* As = sm;                 // [2][ASZ]
    float* Ws = sm + 2 * ASZ;       // [2][WSZ]

    const int tid  = threadIdx.x;
    const int lane = tid & 31;
    const int wid  = tid >> 5;
    const int mw   = (wid & 3) * 32;     // warp m offset in block
    const int nw   = (wid >> 2) * 64;    // warp n offset in block
    const int gr   = lane >> 2;          // 0..7
    const int gc   = lane & 3;           // 0..3
    const int m0   = blockIdx.y * 128;
    const int n0   = blockIdx.x * 128;

    float c[2][8][4];
#pragma unroll
    for (int mt = 0; mt < 2; mt++)
#pragma unroll
        for (int nt = 0; nt < 8; nt++)
#pragma unroll
            for (int j = 0; j < 4; j++) c[mt][nt][j] = 0.f;

    stage_tiles<WMODE>(A, W, As, Ws, m0, n0, 0, tid);
    __syncthreads();

    for (int i = 0; i < NKT; i++) {
        const int p = i & 1;
        if (i + 1 < NKT)
            stage_tiles<WMODE>(A, W, As + (p ^ 1) * ASZ, Ws + (p ^ 1) * WSZ,
                               m0, n0, (i + 1) * 32, tid);

        const float* as = As + p * ASZ + mw * PAD_A;
        const float* ws = Ws + p * WSZ + nw;
#pragma unroll
        for (int ks = 0; ks < 32; ks += 8) {
            uint32_t af[2][4];
#pragma unroll
            for (int mt = 0; mt < 2; mt++) {
                const float* ap = as + (mt * 16 + gr) * PAD_A + ks + gc;
                af[mt][0] = __float_as_uint(ap[0]);
                af[mt][1] = __float_as_uint(ap[8 * PAD_A]);
                af[mt][2] = __float_as_uint(ap[4]);
                af[mt][3] = __float_as_uint(ap[8 * PAD_A + 4]);
            }
            uint32_t bf[8][2];
#pragma unroll
            for (int nt = 0; nt < 8; nt++) {
                const float* bp = ws + (ks + gc) * PAD_W + nt * 8 + gr;
                bf[nt][0] = __float_as_uint(bp[0]);
                bf[nt][1] = __float_as_uint(bp[4 * PAD_W]);
            }
#pragma unroll
            for (int mt = 0; mt < 2; mt++)
#pragma unroll
                for (int nt = 0; nt < 8; nt++)
                    mma_tf32(c[mt][nt], af[mt], bf[nt]);
        }
        __syncthreads();
    }

    // Epilogue: C[m][n], m = m0+mw+mt*16+gr(+8), n = n0+nw+nt*8+2*gc(+1)
#pragma unroll
    for (int mt = 0; mt < 2; mt++) {
#pragma unroll
        for (int half = 0; half < 2; half++) {
            int m = m0 + mw + mt * 16 + gr + half * 8;
            int bb = m >> 11, ss = m & (S_ - 1);
#pragma unroll
            for (int nt = 0; nt < 8; nt++) {
                int n = n0 + nw + nt * 8 + 2 * gc;
                float2 val;
                val.x = c[mt][nt][half * 2 + 0] + bias[n];
                val.y = c[mt][nt][half * 2 + 1] + bias[n + 1];
                if (WMODE == 0) {
                    int h = n >> 6, e = n & 63;
                    *(float2*)(out + (((size_t)bb * H_ + h) * S_ + ss) * DH + e) = val;
                } else {
                    *(float2*)(out + (size_t)m * DM + n) = val;
                }
            }
        }
    }
}

// -------------------------- fp32 flash attention (unchanged) ----------------
__global__ void attn64(const float* __restrict__ Q, const float* __restrict__ K,
                       const float* __restrict__ V, float* __restrict__ O)
{
    extern __shared__ float sm[];
    float* Qs = sm;
    float* Ks = Qs + 64 * 68;
    float* Pt = Ks + 64 * 68;
    float* Vs = Pt + 64 * 65;

    const int tid = threadIdx.x;
    const int ty  = tid >> 3;
    const int tx  = tid & 7;
    const int bh  = blockIdx.y;
    const int q0  = blockIdx.x * 64;

    const float* Qp = Q + ((size_t)bh * S_ + q0) * DH;
    const float* Kp = K + (size_t)bh * S_ * DH;
    const float* Vp = V + (size_t)bh * S_ * DH;

#pragma unroll
    for (int it = 0; it < 8; it++) {
        int idx = tid + it * 128;
        int r   = idx >> 4;
        int c4  = (idx & 15) * 4;
        float4 v = *(const float4*)(Qp + (size_t)r * DH + c4);
        Qs[(c4 + 0) * 68 + r] = v.x; Qs[(c4 + 1) * 68 + r] = v.y;
        Qs[(c4 + 2) * 68 + r] = v.z; Qs[(c4 + 3) * 68 + r] = v.w;
    }

    float m[4], l[4], acc[4][8];
#pragma unroll
    for (int i = 0; i < 4; i++) {
        m[i] = -INFINITY; l[i] = 0.f;
#pragma unroll
        for (int j = 0; j < 8; j++) acc[i][j] = 0.f;
    }

    for (int kt = 0; kt < S_; kt += 64) {
        __syncthreads();
#pragma unroll
        for (int it = 0; it < 8; it++) {
            int idx = tid + it * 128;
            int r   = idx >> 4;
            int c4  = (idx & 15) * 4;
            float4 kv = *(const float4*)(Kp + (size_t)(kt + r) * DH + c4);
            Ks[(c4 + 0) * 68 + r] = kv.x; Ks[(c4 + 1) * 68 + r] = kv.y;
            Ks[(c4 + 2) * 68 + r] = kv.z; Ks[(c4 + 3) * 68 + r] = kv.w;
            float4 vv = *(const float4*)(Vp + (size_t)(kt + r) * DH + c4);
            *(float4*)&Vs[r * 64 + c4] = vv;
        }
        __syncthreads();

        float s[4][8];
#pragma unroll
        for (int i = 0; i < 4; i++)
#pragma unroll
            for (int j = 0; j < 8; j++) s[i][j] = 0.f;

#pragma unroll 16
        for (int kk = 0; kk < 64; kk++) {
            float4 a4 = *(const float4*)&Qs[kk * 68 + ty * 4];
            float b[8];
            *(float4*)&b[0] = *(const float4*)&Ks[kk * 68 + tx * 8];
            *(float4*)&b[4] = *(const float4*)&Ks[kk * 68 + tx * 8 + 4];
            float a[4] = {a4.x, a4.y, a4.z, a4.w};
#pragma unroll
            for (int i = 0; i < 4; i++)
#pragma unroll
                for (int j = 0; j < 8; j++)
                    s[i][j] = fmaf(a[i], b[j], s[i][j]);
        }

#pragma unroll
        for (int i = 0; i < 4; i++) {
            float tmax = -INFINITY;
#pragma unroll
            for (int j = 0; j < 8; j++) {
                s[i][j] *= 0.125f;
                tmax = fmaxf(tmax, s[i][j]);
            }
            tmax = fmaxf(tmax, __shfl_xor_sync(0xffffffffu, tmax, 1));
            tmax = fmaxf(tmax, __shfl_xor_sync(0xffffffffu, tmax, 2));
            tmax = fmaxf(tmax, __shfl_xor_sync(0xffffffffu, tmax, 4));
            float mnew = fmaxf(m[i], tmax);
            float psum = 0.f;
#pragma unroll
            for (int j = 0; j < 8; j++) {
                float p = __expf(s[i][j] - mnew);
                s[i][j] = p;
                psum += p;
            }
            psum += __shfl_xor_sync(0xffffffffu, psum, 1);
            psum += __shfl_xor_sync(0xffffffffu, psum, 2);
            psum += __shfl_xor_sync(0xffffffffu, psum, 4);
            float fac = __expf(m[i] - mnew);
            l[i] = l[i] * fac + psum;
            m[i] = mnew;
#pragma unroll
            for (int j = 0; j < 8; j++) acc[i][j] *= fac;
#pragma unroll
            for (int j = 0; j < 8; j++)
                Pt[(tx * 8 + j) * 65 + ty * 4 + i] = s[i][j];
        }
        __syncthreads();

#pragma unroll 16
        for (int k = 0; k < 64; k++) {
            float p[4];
#pragma unroll
            for (int i = 0; i < 4; i++) p[i] = Pt[k * 65 + ty * 4 + i];
            float b[8];
            *(float4*)&b[0] = *(const float4*)&Vs[k * 64 + tx * 8];
            *(float4*)&b[4] = *(const float4*)&Vs[k * 64 + tx * 8 + 4];
#pragma unroll
            for (int i = 0; i < 4; i++)
#pragma unroll
                for (int j = 0; j < 8; j++)
                    acc[i][j] = fmaf(p[i], b[j], acc[i][j]);
        }
    }

    const int b = bh >> 4, h = bh & 15;
#pragma unroll
    for (int i = 0; i < 4; i++) {
        float inv = 1.f / l[i];
        int q = q0 + ty * 4 + i;
        float* op = O + ((size_t)b * S_ + q) * DM + h * DH + tx * 8;
#pragma unroll
        for (int j = 0; j < 8; j++) op[j] = acc[i][j] * inv;
    }
}

// ---------------------------------------------------------------------------
extern "C" void kernel_launch(void* const* d_in, const int* in_sizes, int n_in,
                              void* d_out, int out_size)
{
    (void)in_sizes; (void)n_in; (void)out_size;
    const float* x  = (const float*)d_in[0];
    const float* WQ = (const float*)d_in[1];
    const float* WK = (const float*)d_in[2];
    const float* WV = (const float*)d_in[3];
    const float* WO = (const float*)d_in[4];
    const float* bQ = (const float*)d_in[5];
    const float* bK = (const float*)d_in[6];
    const float* bV = (const float*)d_in[7];
    const float* bO = (const float*)d_in[8];
    float* out = (float*)d_out;

    void *pq, *pk, *pv, *po;
    cudaGetSymbolAddress(&pq, g_q);
    cudaGetSymbolAddress(&pk, g_k);
    cudaGetSymbolAddress(&pv, g_v);
    cudaGetSymbolAddress(&po, g_o);

    static int attr_set = 0;
    const int attn_smem = (64 * 68 * 2 + 64 * 65 + 64 * 64) * 4;  // 67840
    if (!attr_set) {
        cudaFuncSetAttribute(attn64, cudaFuncAttributeMaxDynamicSharedMemorySize,
                             attn_smem);
        cudaFuncSetAttribute(gemm_mma<0>, cudaFuncAttributeMaxDynamicSharedMemorySize,
                             GSMEM);
        cudaFuncSetAttribute(gemm_mma<1>, cudaFuncAttributeMaxDynamicSharedMemorySize,
                             GSMEM);
        attr_set = 1;
    }

    dim3 ggrid(DM / 128, MTOT / 128);   // (8, 64)
    gemm_mma<0><<<ggrid, 256, GSMEM>>>(x, WQ, bQ, (float*)pq);
    gemm_mma<0><<<ggrid, 256, GSMEM>>>(x, WK, bK, (float*)pk);
    gemm_mma<0><<<ggrid, 256, GSMEM>>>(x, WV, bV, (float*)pv);

    dim3 agrid(S_ / 64, B_ * H_);       // (32, 64)
    attn64<<<agrid, 128, attn_smem>>>((const float*)pq, (const float*)pk,
                                      (const float*)pv, (float*)po);

    gemm_mma<1><<<ggrid, 256, GSMEM>>>((const float*)po, WO, bO, out);
}

// round 4
// speedup vs baseline: 5.0563x; 2.9336x over previous
#include <cuda_runtime.h>
#include <math.h>
#include <stdint.h>

#define B_   4
#define S_   2048
#define H_   16
#define DH   64
#define DM   1024
#define MTOT (B_*S_)   // 8192

// -------------------------- device scratch (no allocs) ---------------------
__device__ float g_q[(size_t)B_*H_*S_*DH];   // [B][H][S][DH]
__device__ float g_k[(size_t)B_*H_*S_*DH];
__device__ float g_v[(size_t)B_*H_*S_*DH];
__device__ float g_o[(size_t)B_*S_*DM];      // attention out [B][S][H*DH]

__device__ __forceinline__ uint32_t f2tf(float x) {   // round-to-nearest tf32
    uint32_t r;
    asm("cvt.rna.tf32.f32 %0, %1;" : "=r"(r) : "f"(x));
    return r;
}
__device__ __forceinline__ void mma_tf32(float c[4], const uint32_t a[4],
                                         const uint32_t b[2]) {
    asm volatile(
        "mma.sync.aligned.m16n8k8.row.col.f32.tf32.tf32.f32 "
        "{%0,%1,%2,%3}, {%4,%5,%6,%7}, {%8,%9}, {%0,%1,%2,%3};"
        : "+f"(c[0]), "+f"(c[1]), "+f"(c[2]), "+f"(c[3])
        : "r"(a[0]), "r"(a[1]), "r"(a[2]), "r"(a[3]), "r"(b[0]), "r"(b[1]));
}

// ---------------------------------------------------------------------------
// Tensor-core tf32 GEMM (unchanged from round 3 — verified)
// ---------------------------------------------------------------------------
#define PAD_A 36
#define PAD_W 136
#define ASZ (128 * PAD_A)
#define WSZ (32 * PAD_W)
#define GSMEM ((2 * (ASZ + WSZ)) * 4)   // 71680 bytes
#define NKT (DM / 32)

template<int WMODE>
__device__ __forceinline__ void stage_tiles(
    const float* __restrict__ A, const float* __restrict__ W,
    float* __restrict__ as, float* __restrict__ ws,
    int m0, int n0, int k0, int tid)
{
#pragma unroll
    for (int i = 0; i < 4; i++) {
        int idx = tid + i * 256;
        int r   = idx >> 3;
        int c4  = (idx & 7) << 2;
        float4 v = *(const float4*)(A + (size_t)(m0 + r) * DM + k0 + c4);
        float4 o;
        o.x = __uint_as_float(f2tf(v.x)); o.y = __uint_as_float(f2tf(v.y));
        o.z = __uint_as_float(f2tf(v.z)); o.w = __uint_as_float(f2tf(v.w));
        *(float4*)(as + r * PAD_A + c4) = o;
    }
#pragma unroll
    for (int i = 0; i < 4; i++) {
        int idx = tid + i * 256;
        int r   = idx >> 5;
        int c4  = (idx & 31) << 2;
        const float* wp;
        if (WMODE == 0) {
            int n = n0 + c4, h = n >> 6, e = n & 63;
            wp = W + ((size_t)h * DM + (k0 + r)) * 64 + e;
        } else {
            wp = W + (size_t)(k0 + r) * DM + n0 + c4;
        }
        float4 v = *(const float4*)wp;
        float4 o;
        o.x = __uint_as_float(f2tf(v.x)); o.y = __uint_as_float(f2tf(v.y));
        o.z = __uint_as_float(f2tf(v.z)); o.w = __uint_as_float(f2tf(v.w));
        *(float4*)(ws + r * PAD_W + c4) = o;
    }
}

template<int WMODE>
__global__ void __launch_bounds__(256, 2)
gemm_mma(const float* __restrict__ A, const float* __restrict__ W,
         const float* __restrict__ bias, float* __restrict__ out)
{
    extern __shared__ float sm[];
    float* As = sm;
    float* Ws = sm + 2 * ASZ;

    const int tid  = threadIdx.x;
    const int lane = tid & 31;
    const int wid  = tid >> 5;
    const int mw   = (wid & 3) * 32;
    const int nw   = (wid >> 2) * 64;
    const int gr   = lane >> 2;
    const int gc   = lane & 3;
    const int m0   = blockIdx.y * 128;
    const int n0   = blockIdx.x * 128;

    float c[2][8][4];
#pragma unroll
    for (int mt = 0; mt < 2; mt++)
#pragma unroll
        for (int nt = 0; nt < 8; nt++)
#pragma unroll
            for (int j = 0; j < 4; j++) c[mt][nt][j] = 0.f;

    stage_tiles<WMODE>(A, W, As, Ws, m0, n0, 0, tid);
    __syncthreads();

    for (int i = 0; i < NKT; i++) {
        const int p = i & 1;
        if (i + 1 < NKT)
            stage_tiles<WMODE>(A, W, As + (p ^ 1) * ASZ, Ws + (p ^ 1) * WSZ,
                               m0, n0, (i + 1) * 32, tid);

        const float* as = As + p * ASZ + mw * PAD_A;
        const float* ws = Ws + p * WSZ + nw;
#pragma unroll
        for (int ks = 0; ks < 32; ks += 8) {
            uint32_t af[2][4];
#pragma unroll
            for (int mt = 0; mt < 2; mt++) {
                const float* ap = as + (mt * 16 + gr) * PAD_A + ks + gc;
                af[mt][0] = __float_as_uint(ap[0]);
                af[mt][1] = __float_as_uint(ap[8 * PAD_A]);
                af[mt][2] = __float_as_uint(ap[4]);
                af[mt][3] = __float_as_uint(ap[8 * PAD_A + 4]);
            }
            uint32_t bf[8][2];
#pragma unroll
            for (int nt = 0; nt < 8; nt++) {
                const float* bp = ws + (ks + gc) * PAD_W + nt * 8 + gr;
                bf[nt][0] = __float_as_uint(bp[0]);
                bf[nt][1] = __float_as_uint(bp[4 * PAD_W]);
            }
#pragma unroll
            for (int mt = 0; mt < 2; mt++)
#pragma unroll
                for (int nt = 0; nt < 8; nt++)
                    mma_tf32(c[mt][nt], af[mt], bf[nt]);
        }
        __syncthreads();
    }

#pragma unroll
    for (int mt = 0; mt < 2; mt++) {
#pragma unroll
        for (int half = 0; half < 2; half++) {
            int m = m0 + mw + mt * 16 + gr + half * 8;
            int bb = m >> 11, ss = m & (S_ - 1);
#pragma unroll
            for (int nt = 0; nt < 8; nt++) {
                int n = n0 + nw + nt * 8 + 2 * gc;
                float2 val;
                val.x = c[mt][nt][half * 2 + 0] + bias[n];
                val.y = c[mt][nt][half * 2 + 1] + bias[n + 1];
                if (WMODE == 0) {
                    int h = n >> 6, e = n & 63;
                    *(float2*)(out + (((size_t)bb * H_ + h) * S_ + ss) * DH + e) = val;
                } else {
                    *(float2*)(out + (size_t)m * DM + n) = val;
                }
            }
        }
    }
}

// ---------------------------------------------------------------------------
// Tensor-core tf32 flash attention.
// Block: 128 queries x one (b,h). 4 warps, warp tile = 32 q (2 m16 tiles).
// K-tile = 64 keys. Online softmax in registers; P via per-warp smem tile.
// smem: Qs[128][68], Ks[64][68], Vs[64][68], Pt[128][68]  = 104448 B.
// ---------------------------------------------------------------------------
#define AST 68
#define ATT_SMEM ((128*AST + 64*AST + 64*AST + 128*AST) * 4)

__global__ void __launch_bounds__(128, 2)
attn_mma(const float* __restrict__ Q, const float* __restrict__ K,
         const float* __restrict__ V, float* __restrict__ O)
{
    extern __shared__ float sm[];
    float* Qs = sm;                    // [128][AST]
    float* Ks = Qs + 128 * AST;        // [64][AST]
    float* Vs = Ks + 64 * AST;         // [64][AST]
    float* Pt = Vs + 64 * AST;         // [128][AST]

    const int tid  = threadIdx.x;
    const int lane = tid & 31;
    const int wid  = tid >> 5;
    const int mw   = wid * 32;
    const int gr   = lane >> 2;
    const int gc   = lane & 3;
    const int bh   = blockIdx.y;
    const int q0   = blockIdx.x * 128;

    const float* Qp = Q + ((size_t)bh * S_ + q0) * DH;
    const float* Kp = K + (size_t)bh * S_ * DH;
    const float* Vp = V + (size_t)bh * S_ * DH;

    // Stage Q (scaled by 1/sqrt(64), tf32-rounded): 128 x 64
#pragma unroll
    for (int i = 0; i < 16; i++) {
        int idx = tid + i * 128;          // 0..2047 float4s
        int r   = idx >> 4;
        int c4  = (idx & 15) << 2;
        float4 v = *(const float4*)(Qp + (size_t)r * DH + c4);
        float4 o;
        o.x = __uint_as_float(f2tf(v.x * 0.125f));
        o.y = __uint_as_float(f2tf(v.y * 0.125f));
        o.z = __uint_as_float(f2tf(v.z * 0.125f));
        o.w = __uint_as_float(f2tf(v.w * 0.125f));
        *(float4*)(Qs + r * AST + c4) = o;
    }

    float mrow[2][2], lrow[2][2], co[2][8][4];
#pragma unroll
    for (int mt = 0; mt < 2; mt++)
#pragma unroll
        for (int hf = 0; hf < 2; hf++) { mrow[mt][hf] = -INFINITY; lrow[mt][hf] = 0.f; }
#pragma unroll
    for (int mt = 0; mt < 2; mt++)
#pragma unroll
        for (int nt = 0; nt < 8; nt++)
#pragma unroll
            for (int j = 0; j < 4; j++) co[mt][nt][j] = 0.f;

    for (int kt = 0; kt < S_; kt += 64) {
        __syncthreads();   // prior iter's Vs reads complete
        // Stage K, V tiles (64 x 64 each, tf32-rounded)
#pragma unroll
        for (int i = 0; i < 8; i++) {
            int idx = tid + i * 128;      // 0..1023 float4s
            int r   = idx >> 4;
            int c4  = (idx & 15) << 2;
            float4 kv = *(const float4*)(Kp + (size_t)(kt + r) * DH + c4);
            float4 ok;
            ok.x = __uint_as_float(f2tf(kv.x)); ok.y = __uint_as_float(f2tf(kv.y));
            ok.z = __uint_as_float(f2tf(kv.z)); ok.w = __uint_as_float(f2tf(kv.w));
            *(float4*)(Ks + r * AST + c4) = ok;
            float4 vv = *(const float4*)(Vp + (size_t)(kt + r) * DH + c4);
            float4 ov;
            ov.x = __uint_as_float(f2tf(vv.x)); ov.y = __uint_as_float(f2tf(vv.y));
            ov.z = __uint_as_float(f2tf(vv.z)); ov.w = __uint_as_float(f2tf(vv.w));
            *(float4*)(Vs + r * AST + c4) = ov;
        }
        __syncthreads();

        // ---- S = Q @ K^T : M=32(q) N=64(key) K=64(d) per warp ----
        float s[2][8][4];
#pragma unroll
        for (int mt = 0; mt < 2; mt++)
#pragma unroll
            for (int nt = 0; nt < 8; nt++)
#pragma unroll
                for (int j = 0; j < 4; j++) s[mt][nt][j] = 0.f;

#pragma unroll
        for (int ks = 0; ks < 8; ks++) {
            uint32_t aq[2][4];
#pragma unroll
            for (int mt = 0; mt < 2; mt++) {
                const float* ap = Qs + (mw + mt * 16 + gr) * AST + ks * 8 + gc;
                aq[mt][0] = __float_as_uint(ap[0]);
                aq[mt][1] = __float_as_uint(ap[8 * AST]);
                aq[mt][2] = __float_as_uint(ap[4]);
                aq[mt][3] = __float_as_uint(ap[8 * AST + 4]);
            }
            uint32_t bk[8][2];
#pragma unroll
            for (int nt = 0; nt < 8; nt++) {
                const float* bp = Ks + (nt * 8 + gr) * AST + ks * 8 + gc;
                bk[nt][0] = __float_as_uint(bp[0]);
                bk[nt][1] = __float_as_uint(bp[4]);
            }
#pragma unroll
            for (int mt = 0; mt < 2; mt++)
#pragma unroll
                for (int nt = 0; nt < 8; nt++)
                    mma_tf32(s[mt][nt], aq[mt], bk[nt]);
        }

        // ---- online softmax (rows gr, gr+8 per mt; lanes gc 0..3 share row) ----
#pragma unroll
        for (int mt = 0; mt < 2; mt++) {
#pragma unroll
            for (int hf = 0; hf < 2; hf++) {
                float mx = -INFINITY;
#pragma unroll
                for (int nt = 0; nt < 8; nt++) {
                    mx = fmaxf(mx, s[mt][nt][hf * 2]);
                    mx = fmaxf(mx, s[mt][nt][hf * 2 + 1]);
                }
                mx = fmaxf(mx, __shfl_xor_sync(0xffffffffu, mx, 1));
                mx = fmaxf(mx, __shfl_xor_sync(0xffffffffu, mx, 2));
                float mnew = fmaxf(mrow[mt][hf], mx);
                float fac  = __expf(mrow[mt][hf] - mnew);
                float psum = 0.f;
#pragma unroll
                for (int nt = 0; nt < 8; nt++) {
#pragma unroll
                    for (int j = 0; j < 2; j++) {
                        float p = __expf(s[mt][nt][hf * 2 + j] - mnew);
                        s[mt][nt][hf * 2 + j] = p;
                        psum += p;
                    }
                }
                psum += __shfl_xor_sync(0xffffffffu, psum, 1);
                psum += __shfl_xor_sync(0xffffffffu, psum, 2);
                lrow[mt][hf] = lrow[mt][hf] * fac + psum;
                mrow[mt][hf] = mnew;
#pragma unroll
                for (int nt = 0; nt < 8; nt++) {
                    co[mt][nt][hf * 2]     *= fac;
                    co[mt][nt][hf * 2 + 1] *= fac;
                }
            }
        }

        // ---- stash P (tf32) into per-warp smem tile, relayout C->A frag ----
#pragma unroll
        for (int mt = 0; mt < 2; mt++)
#pragma unroll
            for (int hf = 0; hf < 2; hf++) {
                float* pp = Pt + (mw + mt * 16 + gr + 8 * hf) * AST;
#pragma unroll
                for (int nt = 0; nt < 8; nt++) {
                    pp[nt * 8 + 2 * gc]     = __uint_as_float(f2tf(s[mt][nt][hf * 2]));
                    pp[nt * 8 + 2 * gc + 1] = __uint_as_float(f2tf(s[mt][nt][hf * 2 + 1]));
                }
            }
        __syncwarp();

        // ---- O += P @ V : M=32(q) N=64(d) K=64(key) per warp ----
#pragma unroll
        for (int ks = 0; ks < 8; ks++) {
            uint32_t ap[2][4];
#pragma unroll
            for (int mt = 0; mt < 2; mt++) {
                const float* pp = Pt + (mw + mt * 16 + gr) * AST + ks * 8 + gc;
                ap[mt][0] = __float_as_uint(pp[0]);
                ap[mt][1] = __float_as_uint(pp[8 * AST]);
                ap[mt][2] = __float_as_uint(pp[4]);
                ap[mt][3] = __float_as_uint(pp[8 * AST + 4]);
            }
            uint32_t bv[8][2];
#pragma unroll
            for (int nt = 0; nt < 8; nt++) {
                const float* vp = Vs + (ks * 8 + gc) * AST + nt * 8 + gr;
                bv[nt][0] = __float_as_uint(vp[0]);
                bv[nt][1] = __float_as_uint(vp[4 * AST]);
            }
#pragma unroll
            for (int mt = 0; mt < 2; mt++)
#pragma unroll
                for (int nt = 0; nt < 8; nt++)
                    mma_tf32(co[mt][nt], ap[mt], bv[nt]);
        }
    }

    // ---- epilogue: O[b][q][h*64 + d] = co / l ----
    const int b = bh >> 4, h = bh & 15;
#pragma unroll
    for (int mt = 0; mt < 2; mt++) {
#pragma unroll
        for (int hf = 0; hf < 2; hf++) {
            float inv = 1.f / lrow[mt][hf];
            int q = q0 + mw + mt * 16 + gr + 8 * hf;
            float* op = O + ((size_t)b * S_ + q) * DM + h * DH;
#pragma unroll
            for (int nt = 0; nt < 8; nt++) {
                float2 val;
                val.x = co[mt][nt][hf * 2]     * inv;
                val.y = co[mt][nt][hf * 2 + 1] * inv;
                *(float2*)(op + nt * 8 + 2 * gc) = val;
            }
        }
    }
}

// ---------------------------------------------------------------------------
extern "C" void kernel_launch(void* const* d_in, const int* in_sizes, int n_in,
                              void* d_out, int out_size)
{
    (void)in_sizes; (void)n_in; (void)out_size;
    const float* x  = (const float*)d_in[0];
    const float* WQ = (const float*)d_in[1];
    const float* WK = (const float*)d_in[2];
    const float* WV = (const float*)d_in[3];
    const float* WO = (const float*)d_in[4];
    const float* bQ = (const float*)d_in[5];
    const float* bK = (const float*)d_in[6];
    const float* bV = (const float*)d_in[7];
    const float* bO = (const float*)d_in[8];
    float* out = (float*)d_out;

    void *pq, *pk, *pv, *po;
    cudaGetSymbolAddress(&pq, g_q);
    cudaGetSymbolAddress(&pk, g_k);
    cudaGetSymbolAddress(&pv, g_v);
    cudaGetSymbolAddress(&po, g_o);

    static int attr_set = 0;
    if (!attr_set) {
        cudaFuncSetAttribute(attn_mma, cudaFuncAttributeMaxDynamicSharedMemorySize,
                             ATT_SMEM);
        cudaFuncSetAttribute(gemm_mma<0>, cudaFuncAttributeMaxDynamicSharedMemorySize,
                             GSMEM);
        cudaFuncSetAttribute(gemm_mma<1>, cudaFuncAttributeMaxDynamicSharedMemorySize,
                             GSMEM);
        attr_set = 1;
    }

    dim3 ggrid(DM / 128, MTOT / 128);   // (8, 64)
    gemm_mma<0><<<ggrid, 256, GSMEM>>>(x, WQ, bQ, (float*)pq);
    gemm_mma<0><<<ggrid, 256, GSMEM>>>(x, WK, bK, (float*)pk);
    gemm_mma<0><<<ggrid, 256, GSMEM>>>(x, WV, bV, (float*)pv);

    dim3 agrid(S_ / 128, B_ * H_);      // (16, 64)
    attn_mma<<<agrid, 128, ATT_SMEM>>>((const float*)pq, (const float*)pk,
                                       (const float*)pv, (float*)po);

    gemm_mma<1><<<ggrid, 256, GSMEM>>>((const float*)po, WO, bO, out);
}